// round 10
// baseline (speedup 1.0000x reference)
#include <cuda_runtime.h>
#include <cuda_fp16.h>
#include <stdint.h>

// Problem constants
#define NPLANES 32            // B*C = 2*16
#define NTEX    512
#define HT      64
#define WT      64
#define TEXELS  (NTEX*HT*WT)  // 2,097,152 texels; plane stride in x
#define HO      1024
#define WO      1024
#define NPIX    (HO*WO)

#define TILE_T  256                     // texels per transpose tile
#define NTEX_HALF    256                // textures per phase
#define TEXELS_HALF  (NTEX_HALF*HT*WT)  // 1,048,576 texels per phase

// 64 MB half-atlas, reused for both phases. Half of L2 (126 MB) -> freshly
// written lines stay dirty-resident through the following sample pass, and
// phase 1's rewrite updates them in place (no writeback of phase 0 data).
__device__ __half g_atlas[(size_t)TEXELS_HALF * NPLANES];

// ---------------------------------------------------------------------------
// Pass T: transpose + fp32->fp16 for textures [base_texel/4096, +256).
// 32 planes x 256 texels per block; x reads __ldcs (evict-first) so the
// atlas write-allocations own L2.
// ---------------------------------------------------------------------------
__global__ __launch_bounds__(1024) void transpose_kernel(const float* __restrict__ x,
                                                         int base_texel) {
    __shared__ float tile[32][TILE_T + 1];
    const int w    = threadIdx.x >> 5;
    const int lane = threadIdx.x & 31;
    const int tbase = blockIdx.x * TILE_T;          // local texel base in half

    const float4* src4 = (const float4*)(x + (size_t)w * TEXELS + base_texel + tbase);
    const float4 a = __ldcs(&src4[lane]);
    const float4 b = __ldcs(&src4[32 + lane]);
    {
        const int t0 = lane * 4;
        tile[w][t0 + 0] = a.x; tile[w][t0 + 1] = a.y;
        tile[w][t0 + 2] = a.z; tile[w][t0 + 3] = a.w;
        const int t1 = (32 + lane) * 4;
        tile[w][t1 + 0] = b.x; tile[w][t1 + 1] = b.y;
        tile[w][t1 + 2] = b.z; tile[w][t1 + 3] = b.w;
    }
    __syncthreads();

    const int tq = lane >> 3;
    const int c  = lane & 7;
    #pragma unroll
    for (int j = 0; j < 2; j++) {
        const int t = w * 8 + j * 4 + tq;
        const float v0 = tile[4 * c + 0][t];
        const float v1 = tile[4 * c + 1][t];
        const float v2 = tile[4 * c + 2][t];
        const float v3 = tile[4 * c + 3][t];
        const __half2 h0 = __floats2half2_rn(v0, v1);
        const __half2 h1 = __floats2half2_rn(v2, v3);
        uint2 pk;
        pk.x = *(const unsigned int*)&h0;
        pk.y = *(const unsigned int*)&h1;
        *(uint2*)(g_atlas + (size_t)(tbase + t) * NPLANES + 4 * c) = pk;
    }
}

// ---------------------------------------------------------------------------
// Pass S: bilinear gather for pixels whose texture lies in [nbase, nbase+256).
// R7 body (2 pixels/warp via half2 lanes, register-pipelined params), with
// per-pixel predication; each pixel is active in exactly one phase so the
// output is fully written across the two passes.
// ---------------------------------------------------------------------------
__global__ __launch_bounds__(256) void sample_kernel(
    const int*    __restrict__ qidx,
    const float2* __restrict__ uv,
    float*        __restrict__ out,
    int nbase) {

    __shared__ float s[64][33];
    __shared__ int   act[64];
    const int w    = threadIdx.x >> 5;
    const int lane = threadIdx.x & 31;
    const int half = lane >> 4;
    const int j    = lane & 15;
    const int pixbase = blockIdx.x * 64;

    const __half2* atlas = (const __half2*)g_atlas;

    int    rn[4];
    float2 ruv[4];
    #pragma unroll
    for (int i = 0; i < 4; i++) {
        const int pix = pixbase + w * 8 + i * 2 + half;
        rn[i]  = __ldcs(&qidx[pix]);
        ruv[i] = __ldcs(&uv[pix]);
    }

    #pragma unroll
    for (int i = 0; i < 4; i++) {
        const int pl = w * 8 + i * 2 + half;

        const int n = min(max(rn[i], 0), NTEX - 1);
        const int nloc = n - nbase;
        const bool active = (nloc >= 0) && (nloc < NTEX_HALF);
        if (j == 0) act[pl] = active ? 1 : 0;

        if (active) {
            const float2 t = ruv[i];
            const float  u  = t.x * 63.0f;
            const float  v  = t.y * 63.0f;
            const float  x0f = floorf(u);
            const float  y0f = floorf(v);
            const float  wu  = u - x0f;
            const float  wv  = v - y0f;

            int x0 = (int)x0f; x0 = min(max(x0, 0), WT - 1);
            int y0 = (int)y0f; y0 = min(max(y0, 0), HT - 1);
            const int x1 = min(x0 + 1, WT - 1);
            const int y1 = min(y0 + 1, HT - 1);

            const int rb = nloc * (HT * WT);
            const int r0 = rb + y0 * WT;
            const int r1 = rb + y1 * WT;

            const float2 g00 = __half22float2(atlas[(size_t)(r0 + x0) * 16 + j]);
            const float2 g01 = __half22float2(atlas[(size_t)(r0 + x1) * 16 + j]);
            const float2 g10 = __half22float2(atlas[(size_t)(r1 + x0) * 16 + j]);
            const float2 g11 = __half22float2(atlas[(size_t)(r1 + x1) * 16 + j]);

            const float topx = fmaf(wu, g01.x - g00.x, g00.x);
            const float botx = fmaf(wu, g11.x - g10.x, g10.x);
            const float topy = fmaf(wu, g01.y - g00.y, g00.y);
            const float boty = fmaf(wu, g11.y - g10.y, g10.y);

            s[pl][2 * j]     = fmaf(wv, botx - topx, topx);
            s[pl][2 * j + 1] = fmaf(wv, boty - topy, topy);
        }
    }

    __syncthreads();

    const int a0 = act[lane];
    const int a1 = act[32 + lane];
    #pragma unroll
    for (int jj = 0; jj < 4; jj++) {
        const int p = w * 4 + jj;
        float* o = out + (size_t)p * NPIX + pixbase;
        if (a0) __stwt(&o[lane],      s[lane][p]);
        if (a1) __stwt(&o[32 + lane], s[32 + lane][p]);
    }
}

extern "C" void kernel_launch(void* const* d_in, const int* in_sizes, int n_in,
                              void* d_out, int out_size) {
    const float*  x    = (const float*)d_in[0];
    const int*    qidx = (const int*)d_in[1];
    const float2* uv   = (const float2*)d_in[2];
    float*        out  = (float*)d_out;

    // Phase 0: textures [0,256)
    transpose_kernel<<<TEXELS_HALF / TILE_T, 1024>>>(x, 0);
    sample_kernel<<<NPIX / 64, 256>>>(qidx, uv, out, 0);
    // Phase 1: textures [256,512) — overwrites the same atlas buffer in L2
    transpose_kernel<<<TEXELS_HALF / TILE_T, 1024>>>(x, TEXELS_HALF);
    sample_kernel<<<NPIX / 64, 256>>>(qidx, uv, out, NTEX_HALF);
}

// round 11
// speedup vs baseline: 1.4628x; 1.4628x over previous
#include <cuda_runtime.h>
#include <cuda_fp16.h>
#include <stdint.h>

// Problem constants
#define NPLANES 32            // B*C = 2*16
#define NTEX    512
#define HT      64
#define WT      64
#define TEXELS  (NTEX*HT*WT)  // 2,097,152 texels; plane stride in x
#define HO      1024
#define WO      1024
#define NPIX    (HO*WO)

#define TILE_T  256           // texels per transpose tile

// 128 MB transposed fp16 atlas: g_xt_h[texel][channel]; one texel's 32
// channels = one 64B half-line (16 half2).
__device__ __half g_xt_h[(size_t)TEXELS * NPLANES];

// ---------------------------------------------------------------------------
// Pass 1: transpose + fp32->fp16, 32 planes x 256 texels per block.
//  Phase A: warp w = plane w; 2 independent LDG.128 per lane (MLP=2).
//  Phase B: lane = t*4 + c  (t: texel 0..7 within warp's group, c: channel
//           OCT, channels 8c..8c+7). 8 LDS.32 tile[8c+k][t] -> banks
//           (8c+k+t)%32 all distinct per k (conflict-free). Pack 4x half2
//           -> one STG.128; warp writes 8 texels x 64B = 512B contiguous.
// ---------------------------------------------------------------------------
__global__ __launch_bounds__(1024) void transpose_kernel(const float* __restrict__ x) {
    __shared__ float tile[32][TILE_T + 1];   // pitch 257 -> bank (r+t)%32
    const int w    = threadIdx.x >> 5;
    const int lane = threadIdx.x & 31;
    const int tbase = blockIdx.x * TILE_T;

    const float4* src4 = (const float4*)(x + (size_t)w * TEXELS + tbase);
    const float4 a = src4[lane];
    const float4 b = src4[32 + lane];
    {
        const int t0 = lane * 4;
        tile[w][t0 + 0] = a.x; tile[w][t0 + 1] = a.y;
        tile[w][t0 + 2] = a.z; tile[w][t0 + 3] = a.w;
        const int t1 = (32 + lane) * 4;
        tile[w][t1 + 0] = b.x; tile[w][t1 + 1] = b.y;
        tile[w][t1 + 2] = b.z; tile[w][t1 + 3] = b.w;
    }
    __syncthreads();

    // Phase B: one iteration, warp covers texels [w*8, w*8+8).
    const int tq = lane >> 2;          // 0..7 texel within group
    const int c  = lane & 3;           // 0..3 channel oct (channels 8c..8c+7)
    const int t  = w * 8 + tq;         // local texel 0..255

    float v[8];
    #pragma unroll
    for (int k = 0; k < 8; k++) v[k] = tile[8 * c + k][t];

    uint4 pk;
    { const __half2 h = __floats2half2_rn(v[0], v[1]); pk.x = *(const unsigned int*)&h; }
    { const __half2 h = __floats2half2_rn(v[2], v[3]); pk.y = *(const unsigned int*)&h; }
    { const __half2 h = __floats2half2_rn(v[4], v[5]); pk.z = *(const unsigned int*)&h; }
    { const __half2 h = __floats2half2_rn(v[6], v[7]); pk.w = *(const unsigned int*)&h; }
    *(uint4*)(g_xt_h + (size_t)(tbase + t) * NPLANES + 8 * c) = pk;
}

// ---------------------------------------------------------------------------
// Pass 2 (R7, best measured): 2 pixels per warp per iteration via half2
// lanes; register-pipelined param loads; smem-staged coalesced __stwt output.
// ---------------------------------------------------------------------------
__global__ __launch_bounds__(256) void sample_kernel(
    const int*    __restrict__ qidx,
    const float2* __restrict__ uv,
    float*        __restrict__ out) {

    __shared__ float s[64][33];
    const int w    = threadIdx.x >> 5;
    const int lane = threadIdx.x & 31;
    const int half = lane >> 4;
    const int j    = lane & 15;
    const int pixbase = blockIdx.x * 64;

    const __half2* atlas = (const __half2*)g_xt_h;

    int    rn[4];
    float2 ruv[4];
    #pragma unroll
    for (int i = 0; i < 4; i++) {
        const int pix = pixbase + w * 8 + i * 2 + half;
        rn[i]  = __ldcs(&qidx[pix]);
        ruv[i] = __ldcs(&uv[pix]);
    }

    #pragma unroll
    for (int i = 0; i < 4; i++) {
        const int pl = w * 8 + i * 2 + half;

        int n = min(max(rn[i], 0), NTEX - 1);
        const float2 t = ruv[i];
        const float  u  = t.x * 63.0f;
        const float  v  = t.y * 63.0f;
        const float  x0f = floorf(u);
        const float  y0f = floorf(v);
        const float  wu  = u - x0f;
        const float  wv  = v - y0f;

        int x0 = (int)x0f; x0 = min(max(x0, 0), WT - 1);
        int y0 = (int)y0f; y0 = min(max(y0, 0), HT - 1);
        const int x1 = min(x0 + 1, WT - 1);
        const int y1 = min(y0 + 1, HT - 1);

        const int rb = n * (HT * WT);
        const int r0 = rb + y0 * WT;
        const int r1 = rb + y1 * WT;

        const float2 g00 = __half22float2(atlas[(size_t)(r0 + x0) * 16 + j]);
        const float2 g01 = __half22float2(atlas[(size_t)(r0 + x1) * 16 + j]);
        const float2 g10 = __half22float2(atlas[(size_t)(r1 + x0) * 16 + j]);
        const float2 g11 = __half22float2(atlas[(size_t)(r1 + x1) * 16 + j]);

        const float topx = fmaf(wu, g01.x - g00.x, g00.x);
        const float botx = fmaf(wu, g11.x - g10.x, g10.x);
        const float topy = fmaf(wu, g01.y - g00.y, g00.y);
        const float boty = fmaf(wu, g11.y - g10.y, g10.y);

        s[pl][2 * j]     = fmaf(wv, botx - topx, topx);
        s[pl][2 * j + 1] = fmaf(wv, boty - topy, topy);
    }

    __syncthreads();

    #pragma unroll
    for (int jj = 0; jj < 4; jj++) {
        const int p = w * 4 + jj;
        float* o = out + (size_t)p * NPIX + pixbase;
        __stwt(&o[lane],      s[lane][p]);
        __stwt(&o[32 + lane], s[32 + lane][p]);
    }
}

extern "C" void kernel_launch(void* const* d_in, const int* in_sizes, int n_in,
                              void* d_out, int out_size) {
    const float*  x    = (const float*)d_in[0];
    const int*    qidx = (const int*)d_in[1];
    const float2* uv   = (const float2*)d_in[2];
    float*        out  = (float*)d_out;

    transpose_kernel<<<TEXELS / TILE_T, 1024>>>(x);
    sample_kernel<<<NPIX / 64, 256>>>(qidx, uv, out);
}

// round 12
// speedup vs baseline: 1.4677x; 1.0034x over previous
#include <cuda_runtime.h>
#include <cuda_fp16.h>
#include <stdint.h>

// Problem constants
#define NPLANES 32            // B*C = 2*16
#define NTEX    512
#define HT      64
#define WT      64
#define TEXELS  (NTEX*HT*WT)  // 2,097,152 texels; plane stride in x
#define HO      1024
#define WO      1024
#define NPIX    (HO*WO)

#define TILE_T  256           // texels per transpose tile

// 128 MB transposed fp16 atlas: g_xt_h[texel][channel]; one texel's 32
// channels = one 64B half-line (16 half2).
__device__ __half g_xt_h[(size_t)TEXELS * NPLANES];

// ---------------------------------------------------------------------------
// Pass 1 (R11): transpose + fp32->fp16, 32 planes x 256 texels per block.
// Phase B: lane = (texel, channel-oct); 8 conflict-free LDS.32 -> STG.128.
// Ends with a PDL trigger so the sample kernel's atlas-wait can release as
// soon as the last store has issued.
// ---------------------------------------------------------------------------
__global__ __launch_bounds__(1024) void transpose_kernel(const float* __restrict__ x) {
    __shared__ float tile[32][TILE_T + 1];   // pitch 257 -> bank (r+t)%32
    const int w    = threadIdx.x >> 5;
    const int lane = threadIdx.x & 31;
    const int tbase = blockIdx.x * TILE_T;

    const float4* src4 = (const float4*)(x + (size_t)w * TEXELS + tbase);
    const float4 a = src4[lane];
    const float4 b = src4[32 + lane];
    {
        const int t0 = lane * 4;
        tile[w][t0 + 0] = a.x; tile[w][t0 + 1] = a.y;
        tile[w][t0 + 2] = a.z; tile[w][t0 + 3] = a.w;
        const int t1 = (32 + lane) * 4;
        tile[w][t1 + 0] = b.x; tile[w][t1 + 1] = b.y;
        tile[w][t1 + 2] = b.z; tile[w][t1 + 3] = b.w;
    }
    __syncthreads();

    const int tq = lane >> 2;          // 0..7 texel within warp's group
    const int c  = lane & 3;           // 0..3 channel oct
    const int t  = w * 8 + tq;

    float v[8];
    #pragma unroll
    for (int k = 0; k < 8; k++) v[k] = tile[8 * c + k][t];

    uint4 pk;
    { const __half2 h = __floats2half2_rn(v[0], v[1]); pk.x = *(const unsigned int*)&h; }
    { const __half2 h = __floats2half2_rn(v[2], v[3]); pk.y = *(const unsigned int*)&h; }
    { const __half2 h = __floats2half2_rn(v[4], v[5]); pk.z = *(const unsigned int*)&h; }
    { const __half2 h = __floats2half2_rn(v[6], v[7]); pk.w = *(const unsigned int*)&h; }
    *(uint4*)(g_xt_h + (size_t)(tbase + t) * NPLANES + 8 * c) = pk;

#if __CUDA_ARCH__ >= 900
    cudaTriggerProgrammaticLaunchCompletion();
#endif
}

// ---------------------------------------------------------------------------
// Pass 2 (R11 body + PDL): prologue (qidx/uv loads, weight/address math)
// runs overlapped with the transpose tail; cudaGridDependencySynchronize()
// gates only the atlas gathers.
// ---------------------------------------------------------------------------
__global__ __launch_bounds__(256) void sample_kernel(
    const int*    __restrict__ qidx,
    const float2* __restrict__ uv,
    float*        __restrict__ out) {

    __shared__ float s[64][33];
    const int w    = threadIdx.x >> 5;
    const int lane = threadIdx.x & 31;
    const int half = lane >> 4;
    const int j    = lane & 15;
    const int pixbase = blockIdx.x * 64;

    const __half2* atlas = (const __half2*)g_xt_h;

    // Prologue (independent of the atlas): param loads + full address math.
    int    rn[4];
    float2 ruv[4];
    #pragma unroll
    for (int i = 0; i < 4; i++) {
        const int pix = pixbase + w * 8 + i * 2 + half;
        rn[i]  = __ldcs(&qidx[pix]);
        ruv[i] = __ldcs(&uv[pix]);
    }

    int   pr0[4], pr1[4], px0[4], px1[4];
    float pwu[4], pwv[4];
    #pragma unroll
    for (int i = 0; i < 4; i++) {
        const int n = min(max(rn[i], 0), NTEX - 1);
        const float2 t = ruv[i];
        const float  u  = t.x * 63.0f;
        const float  v  = t.y * 63.0f;
        const float  x0f = floorf(u);
        const float  y0f = floorf(v);
        pwu[i] = u - x0f;
        pwv[i] = v - y0f;

        int x0 = (int)x0f; x0 = min(max(x0, 0), WT - 1);
        int y0 = (int)y0f; y0 = min(max(y0, 0), HT - 1);
        px0[i] = x0;
        px1[i] = min(x0 + 1, WT - 1);
        const int rb = n * (HT * WT);
        pr0[i] = rb + y0 * WT;
        pr1[i] = rb + min(y0 + 1, HT - 1) * WT;
    }

#if __CUDA_ARCH__ >= 900
    cudaGridDependencySynchronize();   // wait for transpose's atlas stores
#endif

    #pragma unroll
    for (int i = 0; i < 4; i++) {
        const int pl = w * 8 + i * 2 + half;
        const float wu = pwu[i];
        const float wv = pwv[i];

        const float2 g00 = __half22float2(atlas[(size_t)(pr0[i] + px0[i]) * 16 + j]);
        const float2 g01 = __half22float2(atlas[(size_t)(pr0[i] + px1[i]) * 16 + j]);
        const float2 g10 = __half22float2(atlas[(size_t)(pr1[i] + px0[i]) * 16 + j]);
        const float2 g11 = __half22float2(atlas[(size_t)(pr1[i] + px1[i]) * 16 + j]);

        const float topx = fmaf(wu, g01.x - g00.x, g00.x);
        const float botx = fmaf(wu, g11.x - g10.x, g10.x);
        const float topy = fmaf(wu, g01.y - g00.y, g00.y);
        const float boty = fmaf(wu, g11.y - g10.y, g10.y);

        s[pl][2 * j]     = fmaf(wv, botx - topx, topx);
        s[pl][2 * j + 1] = fmaf(wv, boty - topy, topy);
    }

    __syncthreads();

    #pragma unroll
    for (int jj = 0; jj < 4; jj++) {
        const int p = w * 4 + jj;
        float* o = out + (size_t)p * NPIX + pixbase;
        __stwt(&o[lane],      s[lane][p]);
        __stwt(&o[32 + lane], s[32 + lane][p]);
    }
}

extern "C" void kernel_launch(void* const* d_in, const int* in_sizes, int n_in,
                              void* d_out, int out_size) {
    const float*  x    = (const float*)d_in[0];
    const int*    qidx = (const int*)d_in[1];
    const float2* uv   = (const float2*)d_in[2];
    float*        out  = (float*)d_out;

    transpose_kernel<<<TEXELS / TILE_T, 1024>>>(x);

    // Sample with programmatic dependent launch (overlap prologue with the
    // transpose tail). Fall back to a plain launch if PDL is unavailable;
    // cudaGridDependencySynchronize is a no-op on a non-PDL launch.
    cudaLaunchConfig_t cfg = {};
    cfg.gridDim  = dim3(NPIX / 64);
    cfg.blockDim = dim3(256);
    cudaLaunchAttribute attr[1];
    attr[0].id = cudaLaunchAttributeProgrammaticStreamSerialization;
    attr[0].val.programmaticStreamSerializationAllowed = 1;
    cfg.attrs    = attr;
    cfg.numAttrs = 1;
    cudaError_t err = cudaLaunchKernelEx(&cfg, sample_kernel, qidx, uv, out);
    if (err != cudaSuccess) {
        sample_kernel<<<NPIX / 64, 256>>>(qidx, uv, out);
    }
}

// round 13
// speedup vs baseline: 1.4781x; 1.0071x over previous
#include <cuda_runtime.h>
#include <cuda_fp16.h>
#include <stdint.h>

// Problem constants
#define NPLANES 32            // B*C = 2*16
#define NTEX    512
#define HT      64
#define WT      64
#define TEXELS  (NTEX*HT*WT)  // 2,097,152 texels; plane stride in x
#define HO      1024
#define WO      1024
#define NPIX    (HO*WO)

#define TILE_T  256           // texels per transpose tile

// 128 MB transposed fp16 atlas: g_xt_h[texel][channel]; one texel's 32
// channels = one 64B half-line (16 half2).
__device__ __half g_xt_h[(size_t)TEXELS * NPLANES];

// ---------------------------------------------------------------------------
// Pass 1 (R11/R12): transpose + fp32->fp16, 32 planes x 256 texels per block.
// Phase B: lane = (texel, channel-oct); 8 conflict-free LDS.32 -> STG.128.
// PDL trigger at the end.
// ---------------------------------------------------------------------------
__global__ __launch_bounds__(1024) void transpose_kernel(const float* __restrict__ x) {
    __shared__ float tile[32][TILE_T + 1];   // pitch 257 -> bank (r+t)%32
    const int w    = threadIdx.x >> 5;
    const int lane = threadIdx.x & 31;
    const int tbase = blockIdx.x * TILE_T;

    const float4* src4 = (const float4*)(x + (size_t)w * TEXELS + tbase);
    const float4 a = src4[lane];
    const float4 b = src4[32 + lane];
    {
        const int t0 = lane * 4;
        tile[w][t0 + 0] = a.x; tile[w][t0 + 1] = a.y;
        tile[w][t0 + 2] = a.z; tile[w][t0 + 3] = a.w;
        const int t1 = (32 + lane) * 4;
        tile[w][t1 + 0] = b.x; tile[w][t1 + 1] = b.y;
        tile[w][t1 + 2] = b.z; tile[w][t1 + 3] = b.w;
    }
    __syncthreads();

    const int tq = lane >> 2;          // 0..7 texel within warp's group
    const int c  = lane & 3;           // 0..3 channel oct
    const int t  = w * 8 + tq;

    float v[8];
    #pragma unroll
    for (int k = 0; k < 8; k++) v[k] = tile[8 * c + k][t];

    uint4 pk;
    { const __half2 h = __floats2half2_rn(v[0], v[1]); pk.x = *(const unsigned int*)&h; }
    { const __half2 h = __floats2half2_rn(v[2], v[3]); pk.y = *(const unsigned int*)&h; }
    { const __half2 h = __floats2half2_rn(v[4], v[5]); pk.z = *(const unsigned int*)&h; }
    { const __half2 h = __floats2half2_rn(v[6], v[7]); pk.w = *(const unsigned int*)&h; }
    *(uint4*)(g_xt_h + (size_t)(tbase + t) * NPLANES + 8 * c) = pk;

#if __CUDA_ARCH__ >= 900
    cudaTriggerProgrammaticLaunchCompletion();
#endif
}

// ---------------------------------------------------------------------------
// Pass 2: R12 body, but output stores are __stcs (evict-first streaming).
// Output lines allocate at lowest L2 retention priority, so the atlas's
// normal-priority read lines (~110MB unique, fits 126MB L2) survive for
// their in-kernel reuse instead of being churned by the 128MB write stream.
// ---------------------------------------------------------------------------
__global__ __launch_bounds__(256) void sample_kernel(
    const int*    __restrict__ qidx,
    const float2* __restrict__ uv,
    float*        __restrict__ out) {

    __shared__ float s[64][33];
    const int w    = threadIdx.x >> 5;
    const int lane = threadIdx.x & 31;
    const int half = lane >> 4;
    const int j    = lane & 15;
    const int pixbase = blockIdx.x * 64;

    const __half2* atlas = (const __half2*)g_xt_h;

    // Prologue (independent of the atlas): param loads + address math.
    int    rn[4];
    float2 ruv[4];
    #pragma unroll
    for (int i = 0; i < 4; i++) {
        const int pix = pixbase + w * 8 + i * 2 + half;
        rn[i]  = __ldcs(&qidx[pix]);
        ruv[i] = __ldcs(&uv[pix]);
    }

    int   pr0[4], pr1[4], px0[4], px1[4];
    float pwu[4], pwv[4];
    #pragma unroll
    for (int i = 0; i < 4; i++) {
        const int n = min(max(rn[i], 0), NTEX - 1);
        const float2 t = ruv[i];
        const float  u  = t.x * 63.0f;
        const float  v  = t.y * 63.0f;
        const float  x0f = floorf(u);
        const float  y0f = floorf(v);
        pwu[i] = u - x0f;
        pwv[i] = v - y0f;

        int x0 = (int)x0f; x0 = min(max(x0, 0), WT - 1);
        int y0 = (int)y0f; y0 = min(max(y0, 0), HT - 1);
        px0[i] = x0;
        px1[i] = min(x0 + 1, WT - 1);
        const int rb = n * (HT * WT);
        pr0[i] = rb + y0 * WT;
        pr1[i] = rb + min(y0 + 1, HT - 1) * WT;
    }

#if __CUDA_ARCH__ >= 900
    cudaGridDependencySynchronize();   // wait for transpose's atlas stores
#endif

    #pragma unroll
    for (int i = 0; i < 4; i++) {
        const int pl = w * 8 + i * 2 + half;
        const float wu = pwu[i];
        const float wv = pwv[i];

        const float2 g00 = __half22float2(atlas[(size_t)(pr0[i] + px0[i]) * 16 + j]);
        const float2 g01 = __half22float2(atlas[(size_t)(pr0[i] + px1[i]) * 16 + j]);
        const float2 g10 = __half22float2(atlas[(size_t)(pr1[i] + px0[i]) * 16 + j]);
        const float2 g11 = __half22float2(atlas[(size_t)(pr1[i] + px1[i]) * 16 + j]);

        const float topx = fmaf(wu, g01.x - g00.x, g00.x);
        const float botx = fmaf(wu, g11.x - g10.x, g10.x);
        const float topy = fmaf(wu, g01.y - g00.y, g00.y);
        const float boty = fmaf(wu, g11.y - g10.y, g10.y);

        s[pl][2 * j]     = fmaf(wv, botx - topx, topx);
        s[pl][2 * j + 1] = fmaf(wv, boty - topy, topy);
    }

    __syncthreads();

    #pragma unroll
    for (int jj = 0; jj < 4; jj++) {
        const int p = w * 4 + jj;
        float* o = out + (size_t)p * NPIX + pixbase;
        __stcs(&o[lane],      s[lane][p]);        // evict-first write lines
        __stcs(&o[32 + lane], s[32 + lane][p]);
    }
}

extern "C" void kernel_launch(void* const* d_in, const int* in_sizes, int n_in,
                              void* d_out, int out_size) {
    const float*  x    = (const float*)d_in[0];
    const int*    qidx = (const int*)d_in[1];
    const float2* uv   = (const float2*)d_in[2];
    float*        out  = (float*)d_out;

    transpose_kernel<<<TEXELS / TILE_T, 1024>>>(x);

    cudaLaunchConfig_t cfg = {};
    cfg.gridDim  = dim3(NPIX / 64);
    cfg.blockDim = dim3(256);
    cudaLaunchAttribute attr[1];
    attr[0].id = cudaLaunchAttributeProgrammaticStreamSerialization;
    attr[0].val.programmaticStreamSerializationAllowed = 1;
    cfg.attrs    = attr;
    cfg.numAttrs = 1;
    cudaError_t err = cudaLaunchKernelEx(&cfg, sample_kernel, qidx, uv, out);
    if (err != cudaSuccess) {
        sample_kernel<<<NPIX / 64, 256>>>(qidx, uv, out);
    }
}

// round 14
// speedup vs baseline: 1.6248x; 1.0992x over previous
#include <cuda_runtime.h>
#include <cuda_fp16.h>
#include <stdint.h>

// Problem constants
#define NPLANES 32            // B*C = 2*16
#define NTEX    512
#define HT      64
#define WT      64
#define TEXELS  (NTEX*HT*WT)  // 2,097,152 texels; plane stride in x
#define HO      1024
#define WO      1024
#define NPIX    (HO*WO)

#define TILE_T  256           // texels per transpose tile

// 128 MB transposed fp16 atlas: g_xt_h[texel][channel]; one texel's 32
// channels = one 64B half-line (4 x 16B channel quads).
__device__ __half g_xt_h[(size_t)TEXELS * NPLANES];

// ---------------------------------------------------------------------------
// Pass 1 (R11): transpose + fp32->fp16, 32 planes x 256 texels per block.
// Phase B: lane = (texel, channel-oct); 8 conflict-free LDS.32 -> STG.128.
// PDL trigger at the end.
// ---------------------------------------------------------------------------
__global__ __launch_bounds__(1024) void transpose_kernel(const float* __restrict__ x) {
    __shared__ float tile[32][TILE_T + 1];   // pitch 257 -> bank (r+t)%32
    const int w    = threadIdx.x >> 5;
    const int lane = threadIdx.x & 31;
    const int tbase = blockIdx.x * TILE_T;

    const float4* src4 = (const float4*)(x + (size_t)w * TEXELS + tbase);
    const float4 a = src4[lane];
    const float4 b = src4[32 + lane];
    {
        const int t0 = lane * 4;
        tile[w][t0 + 0] = a.x; tile[w][t0 + 1] = a.y;
        tile[w][t0 + 2] = a.z; tile[w][t0 + 3] = a.w;
        const int t1 = (32 + lane) * 4;
        tile[w][t1 + 0] = b.x; tile[w][t1 + 1] = b.y;
        tile[w][t1 + 2] = b.z; tile[w][t1 + 3] = b.w;
    }
    __syncthreads();

    const int tq = lane >> 2;          // 0..7 texel within warp's group
    const int c  = lane & 3;           // 0..3 channel oct
    const int t  = w * 8 + tq;

    float v[8];
    #pragma unroll
    for (int k = 0; k < 8; k++) v[k] = tile[8 * c + k][t];

    uint4 pk;
    { const __half2 h = __floats2half2_rn(v[0], v[1]); pk.x = *(const unsigned int*)&h; }
    { const __half2 h = __floats2half2_rn(v[2], v[3]); pk.y = *(const unsigned int*)&h; }
    { const __half2 h = __floats2half2_rn(v[4], v[5]); pk.z = *(const unsigned int*)&h; }
    { const __half2 h = __floats2half2_rn(v[6], v[7]); pk.w = *(const unsigned int*)&h; }
    *(uint4*)(g_xt_h + (size_t)(tbase + t) * NPLANES + 8 * c) = pk;

#if __CUDA_ARCH__ >= 900
    cudaTriggerProgrammaticLaunchCompletion();
#endif
}

// ---------------------------------------------------------------------------
// Pass 2: 8 pixels per warp, 4 lanes per pixel, LDG.128 corner gathers.
//  lane = p*4 + c: p = pixel 0..7, c = channel quad (channels 8c..8c+7).
//  One LDG.128 per corner serves all 8 pixels -> 0.5 LDG issues/pixel.
//  8 scalar STS.32 stage results (banks p+8c+k+8w, conflict-free, pitch 33);
//  output phase: coalesced per-plane __stcs (evict-first write lines).
// ---------------------------------------------------------------------------
__global__ __launch_bounds__(256) void sample_kernel(
    const int*    __restrict__ qidx,
    const float2* __restrict__ uv,
    float*        __restrict__ out) {

    __shared__ float s[64][33];
    const int tid  = threadIdx.x;
    const int w    = tid >> 5;
    const int lane = tid & 31;
    const int p    = lane >> 2;        // pixel within warp 0..7
    const int c    = lane & 3;         // channel quad 0..3
    const int pixbase = blockIdx.x * 64;
    const int pl   = w * 8 + p;        // local pixel 0..63
    const int pix  = pixbase + pl;

    // Per-pixel params (4 lanes of a pixel load the same address: broadcast).
    const int    rn = __ldcs(&qidx[pix]);
    const float2 t  = __ldcs(&uv[pix]);

    const int n = min(max(rn, 0), NTEX - 1);
    const float u   = t.x * 63.0f;
    const float v   = t.y * 63.0f;
    const float x0f = floorf(u);
    const float y0f = floorf(v);
    const float wu  = u - x0f;
    const float wv  = v - y0f;

    int x0 = (int)x0f; x0 = min(max(x0, 0), WT - 1);
    int y0 = (int)y0f; y0 = min(max(y0, 0), HT - 1);
    const int x1 = min(x0 + 1, WT - 1);
    const int y1 = min(y0 + 1, HT - 1);

    const int rb = n * (HT * WT);
    const int r0 = rb + y0 * WT;
    const int r1 = rb + y1 * WT;

#if __CUDA_ARCH__ >= 900
    cudaGridDependencySynchronize();   // wait for transpose's atlas stores
#endif

    // Atlas as 16B channel quads: index = texel*4 + c.
    const uint4* atlas4 = (const uint4*)g_xt_h;
    const uint4 q00 = atlas4[(size_t)(r0 + x0) * 4 + c];
    const uint4 q01 = atlas4[(size_t)(r0 + x1) * 4 + c];
    const uint4 q10 = atlas4[(size_t)(r1 + x0) * 4 + c];
    const uint4 q11 = atlas4[(size_t)(r1 + x1) * 4 + c];

    // 8 channels per lane: unpack half2 pairs, fp32 bilinear.
    const unsigned int* a00 = (const unsigned int*)&q00;
    const unsigned int* a01 = (const unsigned int*)&q01;
    const unsigned int* a10 = (const unsigned int*)&q10;
    const unsigned int* a11 = (const unsigned int*)&q11;

    #pragma unroll
    for (int k = 0; k < 4; k++) {
        const float2 g00 = __half22float2(*(const __half2*)&a00[k]);
        const float2 g01 = __half22float2(*(const __half2*)&a01[k]);
        const float2 g10 = __half22float2(*(const __half2*)&a10[k]);
        const float2 g11 = __half22float2(*(const __half2*)&a11[k]);

        const float topx = fmaf(wu, g01.x - g00.x, g00.x);
        const float botx = fmaf(wu, g11.x - g10.x, g10.x);
        const float topy = fmaf(wu, g01.y - g00.y, g00.y);
        const float boty = fmaf(wu, g11.y - g10.y, g10.y);

        s[pl][8 * c + 2 * k]     = fmaf(wv, botx - topx, topx);
        s[pl][8 * c + 2 * k + 1] = fmaf(wv, boty - topy, topy);
    }

    __syncthreads();

    // Output: 32 planes / 8 warps = 4 planes per warp; 64 pixels per plane.
    #pragma unroll
    for (int jj = 0; jj < 4; jj++) {
        const int pp = w * 4 + jj;
        float* o = out + (size_t)pp * NPIX + pixbase;
        __stcs(&o[lane],      s[lane][pp]);
        __stcs(&o[32 + lane], s[32 + lane][pp]);
    }
}

extern "C" void kernel_launch(void* const* d_in, const int* in_sizes, int n_in,
                              void* d_out, int out_size) {
    const float*  x    = (const float*)d_in[0];
    const int*    qidx = (const int*)d_in[1];
    const float2* uv   = (const float2*)d_in[2];
    float*        out  = (float*)d_out;

    transpose_kernel<<<TEXELS / TILE_T, 1024>>>(x);

    cudaLaunchConfig_t cfg = {};
    cfg.gridDim  = dim3(NPIX / 64);
    cfg.blockDim = dim3(256);
    cudaLaunchAttribute attr[1];
    attr[0].id = cudaLaunchAttributeProgrammaticStreamSerialization;
    attr[0].val.programmaticStreamSerializationAllowed = 1;
    cfg.attrs    = attr;
    cfg.numAttrs = 1;
    cudaError_t err = cudaLaunchKernelEx(&cfg, sample_kernel, qidx, uv, out);
    if (err != cudaSuccess) {
        sample_kernel<<<NPIX / 64, 256>>>(qidx, uv, out);
    }
}

// round 15
// speedup vs baseline: 1.6817x; 1.0350x over previous
#include <cuda_runtime.h>
#include <cuda_fp16.h>
#include <stdint.h>

// Problem constants
#define NPLANES 32            // B*C = 2*16
#define NTEX    512
#define HT      64
#define WT      64
#define TEXELS  (NTEX*HT*WT)  // 2,097,152 texels; plane stride in x
#define HO      1024
#define WO      1024
#define NPIX    (HO*WO)

#define TILE_T  256           // texels per transpose tile (2 tiles per block)

// 128 MB transposed fp16 atlas: g_xt_h[texel][channel]; one texel's 32
// channels = one 64B half-line (4 x 16B channel quads).
__device__ __half g_xt_h[(size_t)TEXELS * NPLANES];

// Phase B helper: warp w covers texels [w*8, w*8+8) of the tile.
// lane = (tq, c): 8 conflict-free LDS.32 (banks (8c+k+t)%32) -> one STG.128.
__device__ __forceinline__ void transpose_phaseB(const float (*tile)[TILE_T + 1],
                                                 int w, int lane, int tbase) {
    const int tq = lane >> 2;          // 0..7 texel within warp's group
    const int c  = lane & 3;           // 0..3 channel oct
    const int t  = w * 8 + tq;

    float v[8];
    #pragma unroll
    for (int k = 0; k < 8; k++) v[k] = tile[8 * c + k][t];

    uint4 pk;
    { const __half2 h = __floats2half2_rn(v[0], v[1]); pk.x = *(const unsigned int*)&h; }
    { const __half2 h = __floats2half2_rn(v[2], v[3]); pk.y = *(const unsigned int*)&h; }
    { const __half2 h = __floats2half2_rn(v[4], v[5]); pk.z = *(const unsigned int*)&h; }
    { const __half2 h = __floats2half2_rn(v[6], v[7]); pk.w = *(const unsigned int*)&h; }
    *(uint4*)(g_xt_h + (size_t)(tbase + t) * NPLANES + 8 * c) = pk;
}

__device__ __forceinline__ void sts_tile(float (*tile)[TILE_T + 1],
                                         int w, int lane,
                                         const float4 a, const float4 b) {
    const int t0 = lane * 4;
    tile[w][t0 + 0] = a.x; tile[w][t0 + 1] = a.y;
    tile[w][t0 + 2] = a.z; tile[w][t0 + 3] = a.w;
    const int t1 = (32 + lane) * 4;
    tile[w][t1 + 0] = b.x; tile[w][t1 + 1] = b.y;
    tile[w][t1 + 2] = b.z; tile[w][t1 + 3] = b.w;
}

// ---------------------------------------------------------------------------
// Pass 1: transpose + fp32->fp16, TWO 32x256 tiles per block, software-
// pipelined: tile1's LDG.128s issue before tile0's phase B, hiding global
// latency + barrier drain behind the LDS/STG work.
// ---------------------------------------------------------------------------
__global__ __launch_bounds__(1024) void transpose_kernel(const float* __restrict__ x) {
    __shared__ float tile[32][TILE_T + 1];   // pitch 257 -> bank (r+t)%32
    const int w    = threadIdx.x >> 5;
    const int lane = threadIdx.x & 31;
    const int tbase0 = blockIdx.x * (2 * TILE_T);

    const float4* src0 = (const float4*)(x + (size_t)w * TEXELS + tbase0);

    // Tile 0 loads
    const float4 a0 = src0[lane];
    const float4 b0 = src0[32 + lane];
    sts_tile(tile, w, lane, a0, b0);
    __syncthreads();

    // Prefetch tile 1 (LDGs in flight during tile 0 phase B + barriers)
    const float4 a1 = src0[64 + lane];
    const float4 b1 = src0[96 + lane];

    transpose_phaseB(tile, w, lane, tbase0);
    __syncthreads();

    sts_tile(tile, w, lane, a1, b1);
    __syncthreads();

    transpose_phaseB(tile, w, lane, tbase0 + TILE_T);

#if __CUDA_ARCH__ >= 900
    cudaTriggerProgrammaticLaunchCompletion();
#endif
}

// ---------------------------------------------------------------------------
// Pass 2 (R14, best measured): 8 pixels per warp, 4 lanes per pixel,
// LDG.128 corner gathers; __stcs coalesced output; PDL gate on atlas reads.
// ---------------------------------------------------------------------------
__global__ __launch_bounds__(256) void sample_kernel(
    const int*    __restrict__ qidx,
    const float2* __restrict__ uv,
    float*        __restrict__ out) {

    __shared__ float s[64][33];
    const int tid  = threadIdx.x;
    const int w    = tid >> 5;
    const int lane = tid & 31;
    const int p    = lane >> 2;        // pixel within warp 0..7
    const int c    = lane & 3;         // channel quad 0..3
    const int pixbase = blockIdx.x * 64;
    const int pl   = w * 8 + p;        // local pixel 0..63
    const int pix  = pixbase + pl;

    const int    rn = __ldcs(&qidx[pix]);
    const float2 t  = __ldcs(&uv[pix]);

    const int n = min(max(rn, 0), NTEX - 1);
    const float u   = t.x * 63.0f;
    const float v   = t.y * 63.0f;
    const float x0f = floorf(u);
    const float y0f = floorf(v);
    const float wu  = u - x0f;
    const float wv  = v - y0f;

    int x0 = (int)x0f; x0 = min(max(x0, 0), WT - 1);
    int y0 = (int)y0f; y0 = min(max(y0, 0), HT - 1);
    const int x1 = min(x0 + 1, WT - 1);
    const int y1 = min(y0 + 1, HT - 1);

    const int rb = n * (HT * WT);
    const int r0 = rb + y0 * WT;
    const int r1 = rb + y1 * WT;

#if __CUDA_ARCH__ >= 900
    cudaGridDependencySynchronize();   // wait for transpose's atlas stores
#endif

    const uint4* atlas4 = (const uint4*)g_xt_h;
    const uint4 q00 = atlas4[(size_t)(r0 + x0) * 4 + c];
    const uint4 q01 = atlas4[(size_t)(r0 + x1) * 4 + c];
    const uint4 q10 = atlas4[(size_t)(r1 + x0) * 4 + c];
    const uint4 q11 = atlas4[(size_t)(r1 + x1) * 4 + c];

    const unsigned int* a00 = (const unsigned int*)&q00;
    const unsigned int* a01 = (const unsigned int*)&q01;
    const unsigned int* a10 = (const unsigned int*)&q10;
    const unsigned int* a11 = (const unsigned int*)&q11;

    #pragma unroll
    for (int k = 0; k < 4; k++) {
        const float2 g00 = __half22float2(*(const __half2*)&a00[k]);
        const float2 g01 = __half22float2(*(const __half2*)&a01[k]);
        const float2 g10 = __half22float2(*(const __half2*)&a10[k]);
        const float2 g11 = __half22float2(*(const __half2*)&a11[k]);

        const float topx = fmaf(wu, g01.x - g00.x, g00.x);
        const float botx = fmaf(wu, g11.x - g10.x, g10.x);
        const float topy = fmaf(wu, g01.y - g00.y, g00.y);
        const float boty = fmaf(wu, g11.y - g10.y, g10.y);

        s[pl][8 * c + 2 * k]     = fmaf(wv, botx - topx, topx);
        s[pl][8 * c + 2 * k + 1] = fmaf(wv, boty - topy, topy);
    }

    __syncthreads();

    #pragma unroll
    for (int jj = 0; jj < 4; jj++) {
        const int pp = w * 4 + jj;
        float* o = out + (size_t)pp * NPIX + pixbase;
        __stcs(&o[lane],      s[lane][pp]);
        __stcs(&o[32 + lane], s[32 + lane][pp]);
    }
}

extern "C" void kernel_launch(void* const* d_in, const int* in_sizes, int n_in,
                              void* d_out, int out_size) {
    const float*  x    = (const float*)d_in[0];
    const int*    qidx = (const int*)d_in[1];
    const float2* uv   = (const float2*)d_in[2];
    float*        out  = (float*)d_out;

    transpose_kernel<<<TEXELS / (2 * TILE_T), 1024>>>(x);

    cudaLaunchConfig_t cfg = {};
    cfg.gridDim  = dim3(NPIX / 64);
    cfg.blockDim = dim3(256);
    cudaLaunchAttribute attr[1];
    attr[0].id = cudaLaunchAttributeProgrammaticStreamSerialization;
    attr[0].val.programmaticStreamSerializationAllowed = 1;
    cfg.attrs    = attr;
    cfg.numAttrs = 1;
    cudaError_t err = cudaLaunchKernelEx(&cfg, sample_kernel, qidx, uv, out);
    if (err != cudaSuccess) {
        sample_kernel<<<NPIX / 64, 256>>>(qidx, uv, out);
    }
}